// round 5
// baseline (speedup 1.0000x reference)
#include <cuda_runtime.h>

// Problem constants: B=64, H=64, W=64, n=256, NF=513, L=63*63=3969, alpha^2=25

__device__ float g_state[64 * 64 * 64 * 256];   // [cell=(i*64+j)][b][n]
__device__ float g_A[64 * 513 * 520];           // augmented [513 x 514] per batch, ld=520
__device__ unsigned int g_flags[64 * 64 * 4];   // per (cell, batch-quarter) flags

// ---- packed f32x2 helpers (dual fp32 pipe) ---------------------------------
__device__ __forceinline__ unsigned long long pk2(float a, float b) {
    unsigned long long r;
    asm("mov.b64 %0,{%1,%2};" : "=l"(r) : "f"(a), "f"(b));
    return r;
}
__device__ __forceinline__ void fma2(unsigned long long& d,
                                     unsigned long long a, unsigned long long b) {
    asm("fma.rn.f32x2 %0,%1,%2,%0;" : "+l"(d) : "l"(a), "l"(b));
}
__device__ __forceinline__ void unpk2(unsigned long long v, float& a, float& b) {
    asm("mov.b64 {%0,%1},%2;" : "=f"(a), "=f"(b) : "l"(v));
}

// ---- gpu-scope release/acquire flag ops ------------------------------------
__device__ __forceinline__ unsigned int ld_acq(const unsigned int* p) {
    unsigned int v;
    asm volatile("ld.acquire.gpu.global.u32 %0,[%1];" : "=r"(v) : "l"(p) : "memory");
    return v;
}
__device__ __forceinline__ void st_rel(unsigned int* p) {
    asm volatile("st.release.gpu.global.u32 [%0],%1;" :: "l"(p), "r"(1u) : "memory");
}

__global__ void zero_flags()
{
    int idx = blockIdx.x * blockDim.x + threadIdx.x;
    if (idx < 64 * 64 * 4) g_flags[idx] = 0u;
}

// ---------------------------------------------------------------------------
// Phase 1: persistent wavefront scan. ONE launch.
// 256 blocks = 64 rows x 4 batch-quarters (16 batches), full n=256 per block.
// Left state lives in smem (own previous output) -> only up-flag sync.
// Numerics: per-output k order 0..511 (left then up), identical to R1-R3.
// ---------------------------------------------------------------------------
#define SCAN_SMEM ((2 * 256 * 18 + 2 * 32 * 256) * 4)

__global__ __launch_bounds__(256, 2) void scan_persist(
    const float* __restrict__ x, const float* __restrict__ Win,
    const float* __restrict__ W1, const float* __restrict__ W2)
{
    extern __shared__ float smem[];
    float (*left_s)[18] = (float(*)[18])smem;                    // [n=256][b=16 pad 18]
    float (*up_s)[18]   = (float(*)[18])(smem + 256 * 18);       // [k=256][b]
    float (*w_s)[256]   = (float(*)[256])(smem + 2 * 256 * 18);  // [2*32][256]

    const int bid = (int)blockIdx.x;
    const int i  = bid >> 2;        // row, ascends with bid (scheduling-safe)
    const int bq = bid & 3;
    const int b0 = bq * 16;

    const int tid = (int)threadIdx.x;
    const int tx = tid & 31;        // n-quad owner (n = tx*4 and 128+tx*4)
    const int ty = tid >> 5;        // batch pair (b = ty*2, ty*2+1)
    const bool hasU = (i > 0);

    // zero left_s (j==0 input) and up_s (i==0 input)
    for (int idx = tid; idx < 256 * 18; idx += 256) {
        ((float*)left_s)[idx] = 0.f;
        ((float*)up_s)[idx] = 0.f;
    }
    __syncthreads();

    const float4 win0 = *(const float4*)&Win[tx * 4];
    const float4 win1 = *(const float4*)&Win[128 + tx * 4];

    float4 wr[8];
    auto LOADW = [&](int kc) {
        const int k0 = kc * 32;
        const float* __restrict__ Wm = (k0 < 256) ? W1 : W2;
        const int ks = (k0 < 256) ? k0 : k0 - 256;
#pragma unroll
        for (int t = 0; t < 8; ++t) {
            int fi = tid + t * 256;
            int kl = fi >> 6;
            int cq = fi & 63;
            wr[t] = *(const float4*)&Wm[(ks + kl) * 256 + cq * 4];
        }
    };
    auto STOREW = [&](int buf) {
#pragma unroll
        for (int t = 0; t < 8; ++t) {
            int fi = tid + t * 256;
            int kl = fi >> 6;
            int cq = fi & 63;
            *(float4*)&w_s[buf * 32 + kl][cq * 4] = wr[t];
        }
    };

    for (int j = 0; j < 64; ++j) {
        // wait for row above to publish cell (i-1, j)
        if (hasU) {
            if (tid == 0) {
                const unsigned int* f = &g_flags[((i - 1) * 64 + j) * 4 + bq];
                while (ld_acq(f) == 0u) __nanosleep(32);
            }
        }
        __syncthreads();

        // stage up state transposed: up_s[k][b]
        if (hasU) {
            const int cellU = ((i - 1) * 64 + j) * 64;
            const int bb = tid >> 4;   // 0..15
            const int nq = tid & 15;   // 0..15
            const float* src = &g_state[(cellU + b0 + bb) * 256];
#pragma unroll
            for (int r = 0; r < 16; ++r)
                up_s[nq + 16 * r][bb] = src[nq + 16 * r];
        }
        __syncthreads();

        unsigned long long acc[8];
#pragma unroll
        for (int c = 0; c < 8; ++c) acc[c] = 0ull;

        LOADW(0);
        STOREW(0);

        for (int kc = 0; kc < 16; ++kc) {
            __syncthreads();
            if (kc < 15) LOADW(kc + 1);
            const int buf = (kc & 1) * 32;
            const bool isLeft = (kc < 8);
            const float (*as)[18] = isLeft ? left_s : up_s;
            const int ks = isLeft ? kc * 32 : kc * 32 - 256;
#pragma unroll 8
            for (int kl = 0; kl < 32; ++kl) {
                unsigned long long a01 = *(const unsigned long long*)&as[ks + kl][ty * 2];
                float4 wA = *(const float4*)&w_s[buf + kl][tx * 4];
                float4 wB = *(const float4*)&w_s[buf + kl][128 + tx * 4];
                fma2(acc[0], a01, pk2(wA.x, wA.x));
                fma2(acc[1], a01, pk2(wA.y, wA.y));
                fma2(acc[2], a01, pk2(wA.z, wA.z));
                fma2(acc[3], a01, pk2(wA.w, wA.w));
                fma2(acc[4], a01, pk2(wB.x, wB.x));
                fma2(acc[5], a01, pk2(wB.y, wB.y));
                fma2(acc[6], a01, pk2(wB.z, wB.z));
                fma2(acc[7], a01, pk2(wB.w, wB.w));
            }
            if (kc < 15) STOREW((kc + 1) & 1);
        }
        __syncthreads();   // all reads of left_s done before overwrite

        // epilogue: + x*Win, tanh, store to gmem + left_s
        const int cell = (i * 64 + j) * 64;
        float lo[8], hi[8];
#pragma unroll
        for (int c = 0; c < 8; ++c) unpk2(acc[c], lo[c], hi[c]);

        const int bA = b0 + ty * 2;
        const int bB = bA + 1;
        const float xA = x[(bA * 64 + i) * 64 + j];
        const float xB = x[(bB * 64 + i) * 64 + j];

        float4 oA0, oA1, oB0, oB1;
        oA0.x = tanhf(lo[0] + xA * win0.x); oA0.y = tanhf(lo[1] + xA * win0.y);
        oA0.z = tanhf(lo[2] + xA * win0.z); oA0.w = tanhf(lo[3] + xA * win0.w);
        oA1.x = tanhf(lo[4] + xA * win1.x); oA1.y = tanhf(lo[5] + xA * win1.y);
        oA1.z = tanhf(lo[6] + xA * win1.z); oA1.w = tanhf(lo[7] + xA * win1.w);
        oB0.x = tanhf(hi[0] + xB * win0.x); oB0.y = tanhf(hi[1] + xB * win0.y);
        oB0.z = tanhf(hi[2] + xB * win0.z); oB0.w = tanhf(hi[3] + xB * win0.w);
        oB1.x = tanhf(hi[4] + xB * win1.x); oB1.y = tanhf(hi[5] + xB * win1.y);
        oB1.z = tanhf(hi[6] + xB * win1.z); oB1.w = tanhf(hi[7] + xB * win1.w);

        *(float4*)&g_state[(cell + bA) * 256 + tx * 4] = oA0;
        *(float4*)&g_state[(cell + bA) * 256 + 128 + tx * 4] = oA1;
        *(float4*)&g_state[(cell + bB) * 256 + tx * 4] = oB0;
        *(float4*)&g_state[(cell + bB) * 256 + 128 + tx * 4] = oB1;

        const int blA = ty * 2, blB = blA + 1;
        left_s[tx * 4 + 0][blA] = oA0.x; left_s[tx * 4 + 1][blA] = oA0.y;
        left_s[tx * 4 + 2][blA] = oA0.z; left_s[tx * 4 + 3][blA] = oA0.w;
        left_s[128 + tx * 4 + 0][blA] = oA1.x; left_s[128 + tx * 4 + 1][blA] = oA1.y;
        left_s[128 + tx * 4 + 2][blA] = oA1.z; left_s[128 + tx * 4 + 3][blA] = oA1.w;
        left_s[tx * 4 + 0][blB] = oB0.x; left_s[tx * 4 + 1][blB] = oB0.y;
        left_s[tx * 4 + 2][blB] = oB0.z; left_s[tx * 4 + 3][blB] = oB0.w;
        left_s[128 + tx * 4 + 0][blB] = oB1.x; left_s[128 + tx * 4 + 1][blB] = oB1.y;
        left_s[128 + tx * 4 + 2][blB] = oB1.z; left_s[128 + tx * 4 + 3][blB] = oB1.w;

        __threadfence();
        __syncthreads();
        if (tid == 0) st_rel(&g_flags[(i * 64 + j) * 4 + bq]);
    }
}

// ---------------------------------------------------------------------------
// Phase 2a: HtH tiles -> both triangles of A, += 25 on diagonal.
// Incremental (r,c) staging (no integer division); values bitwise == R3.
// ---------------------------------------------------------------------------
__global__ __launch_bounds__(256) void hth_kernel()
{
    __shared__ __align__(16) float Hd[32][64];
    __shared__ __align__(16) float He[32][64];

    int rem = (int)blockIdx.x;
    int ti = 0;
    while (rem >= 9 - ti) { rem -= 9 - ti; ++ti; }
    const int tj = ti + rem;
    const int b = (int)blockIdx.y;
    const int d0 = ti * 64, e0 = tj * 64;
    const bool dLeft = d0 < 256, dOnes = d0 >= 512;
    const bool eLeft = e0 < 256, eOnes = e0 >= 512;
    const int dColn = dLeft ? d0 : d0 - 256;
    const int eColn = eLeft ? e0 : e0 - 256;

    const int tid = (int)threadIdx.x;
    const int tx = tid & 15, ty = tid >> 4;
    const int dd = tid & 63, kb = tid >> 6;

    int rs[8], cs[8];
#pragma unroll
    for (int t = 0; t < 8; ++t) { rs[t] = 0; cs[t] = kb + t * 4; }

    unsigned long long acc[2][4];
#pragma unroll
    for (int p = 0; p < 2; ++p)
#pragma unroll
        for (int c = 0; c < 4; ++c) acc[p][c] = 0ull;

    for (int l0 = 0; l0 < 3969; l0 += 32) {
        __syncthreads();
#pragma unroll
        for (int t = 0; t < 8; ++t) {
            const int kk = kb + t * 4;
            const int r = rs[t], c = cs[t];
            const bool valid = (r < 63);
            float vd, ve;
            if (dOnes) {
                vd = (valid && dd == 0) ? 1.f : 0.f;
            } else {
                int cellb = dLeft ? ((r + 1) * 64 + c) : (r * 64 + c + 1);
                vd = valid ? g_state[(cellb * 64 + b) * 256 + dColn + dd] : 0.f;
            }
            if (eOnes) {
                ve = (valid && dd == 0) ? 1.f : 0.f;
            } else {
                int cellb = eLeft ? ((r + 1) * 64 + c) : (r * 64 + c + 1);
                ve = valid ? g_state[(cellb * 64 + b) * 256 + eColn + dd] : 0.f;
            }
            Hd[kk][dd] = vd;
            He[kk][dd] = ve;
            int cn = c + 32, rn = r;
            if (cn >= 63) { cn -= 63; ++rn; }
            rs[t] = rn; cs[t] = cn;
        }
        __syncthreads();
#pragma unroll 8
        for (int kk = 0; kk < 32; ++kk) {
            unsigned long long a01 = *(const unsigned long long*)&Hd[kk][ty * 4];
            unsigned long long a23 = *(const unsigned long long*)&Hd[kk][ty * 4 + 2];
            float4 w = *(const float4*)&He[kk][tx * 4];
            unsigned long long wx = pk2(w.x, w.x);
            unsigned long long wy = pk2(w.y, w.y);
            unsigned long long wz = pk2(w.z, w.z);
            unsigned long long ww = pk2(w.w, w.w);
            fma2(acc[0][0], a01, wx); fma2(acc[0][1], a01, wy);
            fma2(acc[0][2], a01, wz); fma2(acc[0][3], a01, ww);
            fma2(acc[1][0], a23, wx); fma2(acc[1][1], a23, wy);
            fma2(acc[1][2], a23, wz); fma2(acc[1][3], a23, ww);
        }
    }

    float v[4][4];
#pragma unroll
    for (int p = 0; p < 2; ++p)
#pragma unroll
        for (int c = 0; c < 4; ++c)
            unpk2(acc[p][c], v[2 * p][c], v[2 * p + 1][c]);

    float* __restrict__ A = g_A + b * 513 * 520;
#pragma unroll
    for (int r = 0; r < 4; ++r) {
        int dr = d0 + ty * 4 + r;
        if (dr >= 513) continue;
#pragma unroll
        for (int c = 0; c < 4; ++c) {
            int e = e0 + tx * 4 + c;
            if (e >= 513) continue;
            float val = v[r][c];
            if (dr == e) val += 25.0f;
            A[dr * 520 + e] = val;
            if (ti != tj) A[e * 520 + dr] = val;
        }
    }
}

// ---------------------------------------------------------------------------
// Phase 2b: HtU -> column 513 of A.  EXACT R3 numerics (sequential (r,c) sum
// per column) — do NOT reassociate; the solve amplifies RHS perturbations.
// ---------------------------------------------------------------------------
__global__ __launch_bounds__(256) void htu_kernel(const float* __restrict__ x)
{
    const int b = (int)blockIdx.x;
    const int dcol = (int)blockIdx.y * 256 + (int)threadIdx.x;
    if (dcol >= 513) return;
    const float* __restrict__ xb = x + b * 4096;
    float acc = 0.f;
    if (dcol < 256) {
        for (int r = 0; r < 63; ++r)
            for (int c = 0; c < 63; ++c)
                acc += xb[(r + 1) * 64 + c + 1] *
                       g_state[(((r + 1) * 64 + c) * 64 + b) * 256 + dcol];
    } else if (dcol < 512) {
        const int d2 = dcol - 256;
        for (int r = 0; r < 63; ++r)
            for (int c = 0; c < 63; ++c)
                acc += xb[(r + 1) * 64 + c + 1] *
                       g_state[((r * 64 + (c + 1)) * 64 + b) * 256 + d2];
    } else {
        for (int r = 0; r < 63; ++r)
            for (int c = 0; c < 63; ++c)
                acc += xb[(r + 1) * 64 + c + 1];
    }
    g_A[(b * 513 + dcol) * 520 + 513] = acc;
}

// ---------------------------------------------------------------------------
// Phase 3: per-batch blocked LU (no pivoting; SPD) + back substitution.
// ---------------------------------------------------------------------------
__global__ __launch_bounds__(512) void solve_kernel(float* __restrict__ out)
{
    __shared__ float P[513 * 17];
    __shared__ __align__(16) float Us[16 * 132];
    __shared__ float red[16];

    const int b = (int)blockIdx.x;
    const int tid = (int)threadIdx.x;
    float* __restrict__ A = g_A + b * 513 * 520;

    for (int k0 = 0; k0 < 513; k0 += 16) {
        const int nb = (513 - k0) < 16 ? (513 - k0) : 16;
        const int nrows = 513 - k0;

        for (int idx = tid; idx < nrows * nb; idx += 512) {
            int rr = idx / nb, cc = idx - rr * nb;
            P[rr * 17 + cc] = A[(k0 + rr) * 520 + (k0 + cc)];
        }
        __syncthreads();

        for (int kk = 0; kk < nb; ++kk) {
            float inv = 1.0f / P[kk * 17 + kk];
            for (int rr = kk + 1 + tid; rr < nrows; rr += 512) {
                float lv = P[rr * 17 + kk] * inv;
                P[rr * 17 + kk] = lv;
                for (int cc = kk + 1; cc < nb; ++cc)
                    P[rr * 17 + cc] -= lv * P[kk * 17 + cc];
            }
            __syncthreads();
        }

        for (int idx = tid; idx < nrows * nb; idx += 512) {
            int rr = idx / nb, cc = idx - rr * nb;
            A[(k0 + rr) * 520 + (k0 + cc)] = P[rr * 17 + cc];
        }
        __syncthreads();

        const int cstart = k0 + nb;
        const int width = 514 - cstart;
        for (int ch = 0; ch < width; ch += 128) {
            int wlen = width - ch; if (wlen > 128) wlen = 128;
            const int wlenp = (wlen + 3) & ~3;
            const int cbase = cstart + ch;

            for (int idx = tid; idx < nb * wlenp; idx += 512) {
                int rr = idx / wlenp, cc = idx - rr * wlenp;
                Us[rr * 132 + cc] = A[(k0 + rr) * 520 + cbase + cc];
            }
            __syncthreads();

            for (int cc = tid; cc < wlenp; cc += 512) {
                float col[16];
                for (int m = 0; m < nb; ++m) col[m] = Us[m * 132 + cc];
                for (int kk = 1; kk < nb; ++kk) {
                    float v = col[kk];
                    for (int m = 0; m < kk; ++m) v -= P[kk * 17 + m] * col[m];
                    col[kk] = v;
                }
                for (int m = 0; m < nb; ++m) {
                    Us[m * 132 + cc] = col[m];
                    A[(k0 + m) * 520 + cbase + cc] = col[m];
                }
            }
            __syncthreads();

            const int trows = nrows - nb;
            const int npr = (trows + 1) >> 1;
            const int ncq = wlenp >> 2;
            for (int idx = tid; idx < npr * ncq; idx += 512) {
                int pr = idx / ncq, cq = idx - pr * ncq;
                int row0 = cstart + pr * 2;
                int cc = cq * 4;
                bool has2 = (pr * 2 + 1) < trows;
                const unsigned long long* pa0 =
                    (const unsigned long long*)&A[row0 * 520 + cbase + cc];
                const unsigned long long* pa1 =
                    (const unsigned long long*)&A[(row0 + 1) * 520 + cbase + cc];
                unsigned long long a00 = pa0[0], a01v = pa0[1];
                unsigned long long a10 = has2 ? pa1[0] : a00;
                unsigned long long a11 = has2 ? pa1[1] : a01v;
                const float* P0 = &P[(row0 - k0) * 17];
                const float* P1 = has2 ? (P0 + 17) : P0;
#pragma unroll
                for (int m = 0; m < 16; ++m) {
                    if (m < nb) {
                        const unsigned long long* pu =
                            (const unsigned long long*)&Us[m * 132 + cc];
                        unsigned long long u01 = pu[0], u23 = pu[1];
                        float p0 = P0[m], p1 = P1[m];
                        unsigned long long np0 = pk2(-p0, -p0);
                        unsigned long long np1 = pk2(-p1, -p1);
                        fma2(a00, u01, np0); fma2(a01v, u23, np0);
                        fma2(a10, u01, np1); fma2(a11, u23, np1);
                    }
                }
                unsigned long long* sa0 =
                    (unsigned long long*)&A[row0 * 520 + cbase + cc];
                sa0[0] = a00; sa0[1] = a01v;
                if (has2) {
                    unsigned long long* sa1 =
                        (unsigned long long*)&A[(row0 + 1) * 520 + cbase + cc];
                    sa1[0] = a10; sa1[1] = a11;
                }
            }
            __syncthreads();
        }
    }

    float* xs = P;
    const int lane = tid & 31, wid = tid >> 5;
    for (int r = 512; r >= 0; --r) {
        float part = 0.f;
        for (int c = r + 1 + tid; c <= 512; c += 512)
            part += A[r * 520 + c] * xs[c];
#pragma unroll
        for (int off = 16; off > 0; off >>= 1)
            part += __shfl_down_sync(0xffffffffu, part, off);
        if (lane == 0) red[wid] = part;
        __syncthreads();
        if (tid == 0) {
            float s = 0.f;
#pragma unroll
            for (int w2 = 0; w2 < 16; ++w2) s += red[w2];
            xs[r] = (A[r * 520 + 513] - s) / A[r * 520 + r];
        }
        __syncthreads();
    }
    for (int i2 = tid; i2 < 513; i2 += 512)
        out[b * 513 + i2] = xs[i2];
}

// ---------------------------------------------------------------------------
extern "C" void kernel_launch(void* const* d_in, const int* in_sizes, int n_in,
                              void* d_out, int out_size)
{
    const float* x   = (const float*)d_in[0];
    const float* Win = (const float*)d_in[1];
    const float* W1  = (const float*)d_in[2];
    const float* W2  = (const float*)d_in[3];
    float* out = (float*)d_out;

    static bool attr_set = false;
    if (!attr_set) {
        cudaFuncSetAttribute(scan_persist,
                             cudaFuncAttributeMaxDynamicSharedMemorySize, SCAN_SMEM);
        attr_set = true;
    }

    zero_flags<<<32, 512>>>();
    scan_persist<<<256, 256, SCAN_SMEM>>>(x, Win, W1, W2);
    hth_kernel<<<dim3(45, 64), 256>>>();
    htu_kernel<<<dim3(64, 3), 256>>>(x);
    solve_kernel<<<64, 512>>>(out);
}

// round 6
// speedup vs baseline: 1.0586x; 1.0586x over previous
#include <cuda_runtime.h>

// Problem constants: B=64, H=64, W=64, n=256, NF=513, L=63*63=3969, alpha^2=25

__device__ float g_state[64 * 64 * 64 * 256];   // [cell=(i*64+j)][b][n]
__device__ float g_A[64 * 513 * 520];           // augmented [513 x 514] per batch, ld=520

// ---- packed f32x2 helpers (dual fp32 pipe) ---------------------------------
__device__ __forceinline__ unsigned long long pk2(float a, float b) {
    unsigned long long r;
    asm("mov.b64 %0,{%1,%2};" : "=l"(r) : "f"(a), "f"(b));
    return r;
}
__device__ __forceinline__ void fma2(unsigned long long& d,
                                     unsigned long long a, unsigned long long b) {
    asm("fma.rn.f32x2 %0,%1,%2,%0;" : "+l"(d) : "l"(a), "l"(b));
}
__device__ __forceinline__ void unpk2(unsigned long long v, float& a, float& b) {
    asm("mov.b64 {%0,%1},%2;" : "=f"(a), "=f"(b) : "l"(v));
}

// ---------------------------------------------------------------------------
// Phase 1: wavefront scan, one launch per anti-diagonal (proven structure).
// grid = (cells, 4, 2): 16 batches x 128 features per block, 256 threads.
// Column-packed f32x2: W pairs load directly as u64 from smem.
// Per-output k order: ascending 0..511 (left then up) — bitwise == R2/R3/R5.
// ---------------------------------------------------------------------------
__global__ __launch_bounds__(256) void scan_diag(
    const float* __restrict__ x, const float* __restrict__ Win,
    const float* __restrict__ W1, const float* __restrict__ W2,
    int d, int i_min)
{
    __shared__ __align__(16) float in_s[2][32][18];   // [buf][k][b(16)+pad]
    __shared__ __align__(16) float w_s[2][32][128];   // [buf][k][n]

    const int i = i_min + (int)blockIdx.x;
    const int j = d - i;
    const int b0 = (int)blockIdx.y * 16;
    const int n0 = (int)blockIdx.z * 128;
    const int tid = (int)threadIdx.x;
    const int tx = tid & 31;    // owns n = n0 + tx*4 .. +3 (2 packed pairs)
    const int ty = tid >> 5;    // owns b = b0 + ty*2, +1

    const bool hasL = (j > 0);
    const bool hasU = (i > 0);
    const int cellL = hasL ? ((i * 64 + (j - 1)) * 64) : 0;
    const int cellU = hasU ? (((i - 1) * 64 + j) * 64) : 0;

    // staging roles
    const int bb = (tid >> 3) & 15;  // 0..15 (only tid<128 stages input)
    const int kq = tid & 7;          // float4 index along k

    unsigned long long acc[2][2];    // [b][npair]
    acc[0][0] = acc[0][1] = acc[1][0] = acc[1][1] = 0ull;

    float4 inr;
    float4 wr[4];

    auto LOADC = [&](int kc) {
        const int k0 = kc * 32;
        const bool isLeft = (k0 < 256);
        const bool has = isLeft ? hasL : hasU;
        const int ks = isLeft ? k0 : (k0 - 256);
        if (tid < 128) {
            inr = make_float4(0.f, 0.f, 0.f, 0.f);
            if (has) {
                const int cell = isLeft ? cellL : cellU;
                inr = *(const float4*)&g_state[(cell + b0 + bb) * 256 + ks + kq * 4];
            }
        }
        const float* __restrict__ Wm = isLeft ? W1 : W2;
#pragma unroll
        for (int t = 0; t < 4; ++t) {
            int fi = tid + t * 256;
            int kl = fi >> 5;
            int cq = fi & 31;
            wr[t] = *(const float4*)&Wm[(ks + kl) * 256 + n0 + cq * 4];
        }
    };
    auto STOREC = [&](int buf) {
        if (tid < 128) {
            in_s[buf][kq * 4 + 0][bb] = inr.x;
            in_s[buf][kq * 4 + 1][bb] = inr.y;
            in_s[buf][kq * 4 + 2][bb] = inr.z;
            in_s[buf][kq * 4 + 3][bb] = inr.w;
        }
#pragma unroll
        for (int t = 0; t < 4; ++t) {
            int fi = tid + t * 256;
            int kl = fi >> 5;
            int cq = fi & 31;
            *(float4*)&w_s[buf][kl][cq * 4] = wr[t];
        }
    };

    LOADC(0);
    STOREC(0);

    for (int kc = 0; kc < 16; ++kc) {
        __syncthreads();
        if (kc < 15) LOADC(kc + 1);
        const int buf = kc & 1;
#pragma unroll 16
        for (int kl = 0; kl < 32; ++kl) {
            float2 a = *(const float2*)&in_s[buf][kl][ty * 2];
            unsigned long long a0 = pk2(a.x, a.x);
            unsigned long long a1 = pk2(a.y, a.y);
            unsigned long long w01 = *(const unsigned long long*)&w_s[buf][kl][tx * 4];
            unsigned long long w23 = *(const unsigned long long*)&w_s[buf][kl][tx * 4 + 2];
            fma2(acc[0][0], a0, w01); fma2(acc[0][1], a0, w23);
            fma2(acc[1][0], a1, w01); fma2(acc[1][1], a1, w23);
        }
        if (kc < 15) STOREC((kc + 1) & 1);
    }

    // epilogue: + x*Win, tanh, store
    const int cell = (i * 64 + j) * 64;
    const float4 wv = *(const float4*)&Win[n0 + tx * 4];
    const int bA = b0 + ty * 2;
    const int bB = bA + 1;
    const float xA = x[(bA * 64 + i) * 64 + j];
    const float xB = x[(bB * 64 + i) * 64 + j];

    float a00, a01v, a02, a03, a10, a11, a12, a13;
    unpk2(acc[0][0], a00, a01v);
    unpk2(acc[0][1], a02, a03);
    unpk2(acc[1][0], a10, a11);
    unpk2(acc[1][1], a12, a13);

    float4 oA, oB;
    oA.x = tanhf(a00 + xA * wv.x); oA.y = tanhf(a01v + xA * wv.y);
    oA.z = tanhf(a02 + xA * wv.z); oA.w = tanhf(a03 + xA * wv.w);
    oB.x = tanhf(a10 + xB * wv.x); oB.y = tanhf(a11 + xB * wv.y);
    oB.z = tanhf(a12 + xB * wv.z); oB.w = tanhf(a13 + xB * wv.w);

    *(float4*)&g_state[(cell + bA) * 256 + n0 + tx * 4] = oA;
    *(float4*)&g_state[(cell + bB) * 256 + n0 + tx * 4] = oB;
}

// ---------------------------------------------------------------------------
// Phase 2a: HtH tiles -> both triangles of A, += 25 on diagonal.
// Incremental (r,c) staging; values bitwise == R3/R5 (passed).
// ---------------------------------------------------------------------------
__global__ __launch_bounds__(256) void hth_kernel()
{
    __shared__ __align__(16) float Hd[32][64];
    __shared__ __align__(16) float He[32][64];

    int rem = (int)blockIdx.x;
    int ti = 0;
    while (rem >= 9 - ti) { rem -= 9 - ti; ++ti; }
    const int tj = ti + rem;
    const int b = (int)blockIdx.y;
    const int d0 = ti * 64, e0 = tj * 64;
    const bool dLeft = d0 < 256, dOnes = d0 >= 512;
    const bool eLeft = e0 < 256, eOnes = e0 >= 512;
    const int dColn = dLeft ? d0 : d0 - 256;
    const int eColn = eLeft ? e0 : e0 - 256;

    const int tid = (int)threadIdx.x;
    const int tx = tid & 15, ty = tid >> 4;
    const int dd = tid & 63, kb = tid >> 6;

    int rs[8], cs[8];
#pragma unroll
    for (int t = 0; t < 8; ++t) { rs[t] = 0; cs[t] = kb + t * 4; }

    unsigned long long acc[2][4];
#pragma unroll
    for (int p = 0; p < 2; ++p)
#pragma unroll
        for (int c = 0; c < 4; ++c) acc[p][c] = 0ull;

    for (int l0 = 0; l0 < 3969; l0 += 32) {
        __syncthreads();
#pragma unroll
        for (int t = 0; t < 8; ++t) {
            const int kk = kb + t * 4;
            const int r = rs[t], c = cs[t];
            const bool valid = (r < 63);
            float vd, ve;
            if (dOnes) {
                vd = (valid && dd == 0) ? 1.f : 0.f;
            } else {
                int cellb = dLeft ? ((r + 1) * 64 + c) : (r * 64 + c + 1);
                vd = valid ? g_state[(cellb * 64 + b) * 256 + dColn + dd] : 0.f;
            }
            if (eOnes) {
                ve = (valid && dd == 0) ? 1.f : 0.f;
            } else {
                int cellb = eLeft ? ((r + 1) * 64 + c) : (r * 64 + c + 1);
                ve = valid ? g_state[(cellb * 64 + b) * 256 + eColn + dd] : 0.f;
            }
            Hd[kk][dd] = vd;
            He[kk][dd] = ve;
            int cn = c + 32, rn = r;
            if (cn >= 63) { cn -= 63; ++rn; }
            rs[t] = rn; cs[t] = cn;
        }
        __syncthreads();
#pragma unroll 8
        for (int kk = 0; kk < 32; ++kk) {
            unsigned long long a01 = *(const unsigned long long*)&Hd[kk][ty * 4];
            unsigned long long a23 = *(const unsigned long long*)&Hd[kk][ty * 4 + 2];
            float4 w = *(const float4*)&He[kk][tx * 4];
            unsigned long long wx = pk2(w.x, w.x);
            unsigned long long wy = pk2(w.y, w.y);
            unsigned long long wz = pk2(w.z, w.z);
            unsigned long long ww = pk2(w.w, w.w);
            fma2(acc[0][0], a01, wx); fma2(acc[0][1], a01, wy);
            fma2(acc[0][2], a01, wz); fma2(acc[0][3], a01, ww);
            fma2(acc[1][0], a23, wx); fma2(acc[1][1], a23, wy);
            fma2(acc[1][2], a23, wz); fma2(acc[1][3], a23, ww);
        }
    }

    float v[4][4];
#pragma unroll
    for (int p = 0; p < 2; ++p)
#pragma unroll
        for (int c = 0; c < 4; ++c)
            unpk2(acc[p][c], v[2 * p][c], v[2 * p + 1][c]);

    float* __restrict__ A = g_A + b * 513 * 520;
#pragma unroll
    for (int r = 0; r < 4; ++r) {
        int dr = d0 + ty * 4 + r;
        if (dr >= 513) continue;
#pragma unroll
        for (int c = 0; c < 4; ++c) {
            int e = e0 + tx * 4 + c;
            if (e >= 513) continue;
            float val = v[r][c];
            if (dr == e) val += 25.0f;
            A[dr * 520 + e] = val;
            if (ti != tj) A[e * 520 + dr] = val;
        }
    }
}

// ---------------------------------------------------------------------------
// Phase 2b: HtU -> column 513 of A.  EXACT R3 numerics (sequential (r,c) sum
// per column) — do NOT reassociate; the solve amplifies RHS perturbations.
// ---------------------------------------------------------------------------
__global__ __launch_bounds__(256) void htu_kernel(const float* __restrict__ x)
{
    const int b = (int)blockIdx.x;
    const int dcol = (int)blockIdx.y * 256 + (int)threadIdx.x;
    if (dcol >= 513) return;
    const float* __restrict__ xb = x + b * 4096;
    float acc = 0.f;
    if (dcol < 256) {
        for (int r = 0; r < 63; ++r)
            for (int c = 0; c < 63; ++c)
                acc += xb[(r + 1) * 64 + c + 1] *
                       g_state[(((r + 1) * 64 + c) * 64 + b) * 256 + dcol];
    } else if (dcol < 512) {
        const int d2 = dcol - 256;
        for (int r = 0; r < 63; ++r)
            for (int c = 0; c < 63; ++c)
                acc += xb[(r + 1) * 64 + c + 1] *
                       g_state[((r * 64 + (c + 1)) * 64 + b) * 256 + d2];
    } else {
        for (int r = 0; r < 63; ++r)
            for (int c = 0; c < 63; ++c)
                acc += xb[(r + 1) * 64 + c + 1];
    }
    g_A[(b * 513 + dcol) * 520 + 513] = acc;
}

// ---------------------------------------------------------------------------
// Phase 3: per-batch blocked LU (no pivoting; SPD) + back substitution.
// ---------------------------------------------------------------------------
__global__ __launch_bounds__(512) void solve_kernel(float* __restrict__ out)
{
    __shared__ float P[513 * 17];
    __shared__ __align__(16) float Us[16 * 132];
    __shared__ float red[16];

    const int b = (int)blockIdx.x;
    const int tid = (int)threadIdx.x;
    float* __restrict__ A = g_A + b * 513 * 520;

    for (int k0 = 0; k0 < 513; k0 += 16) {
        const int nb = (513 - k0) < 16 ? (513 - k0) : 16;
        const int nrows = 513 - k0;

        for (int idx = tid; idx < nrows * nb; idx += 512) {
            int rr = idx / nb, cc = idx - rr * nb;
            P[rr * 17 + cc] = A[(k0 + rr) * 520 + (k0 + cc)];
        }
        __syncthreads();

        for (int kk = 0; kk < nb; ++kk) {
            float inv = 1.0f / P[kk * 17 + kk];
            for (int rr = kk + 1 + tid; rr < nrows; rr += 512) {
                float lv = P[rr * 17 + kk] * inv;
                P[rr * 17 + kk] = lv;
                for (int cc = kk + 1; cc < nb; ++cc)
                    P[rr * 17 + cc] -= lv * P[kk * 17 + cc];
            }
            __syncthreads();
        }

        for (int idx = tid; idx < nrows * nb; idx += 512) {
            int rr = idx / nb, cc = idx - rr * nb;
            A[(k0 + rr) * 520 + (k0 + cc)] = P[rr * 17 + cc];
        }
        __syncthreads();

        const int cstart = k0 + nb;
        const int width = 514 - cstart;
        for (int ch = 0; ch < width; ch += 128) {
            int wlen = width - ch; if (wlen > 128) wlen = 128;
            const int wlenp = (wlen + 3) & ~3;
            const int cbase = cstart + ch;

            for (int idx = tid; idx < nb * wlenp; idx += 512) {
                int rr = idx / wlenp, cc = idx - rr * wlenp;
                Us[rr * 132 + cc] = A[(k0 + rr) * 520 + cbase + cc];
            }
            __syncthreads();

            for (int cc = tid; cc < wlenp; cc += 512) {
                float col[16];
                for (int m = 0; m < nb; ++m) col[m] = Us[m * 132 + cc];
                for (int kk = 1; kk < nb; ++kk) {
                    float v = col[kk];
                    for (int m = 0; m < kk; ++m) v -= P[kk * 17 + m] * col[m];
                    col[kk] = v;
                }
                for (int m = 0; m < nb; ++m) {
                    Us[m * 132 + cc] = col[m];
                    A[(k0 + m) * 520 + cbase + cc] = col[m];
                }
            }
            __syncthreads();

            const int trows = nrows - nb;
            const int npr = (trows + 1) >> 1;
            const int ncq = wlenp >> 2;
            for (int idx = tid; idx < npr * ncq; idx += 512) {
                int pr = idx / ncq, cq = idx - pr * ncq;
                int row0 = cstart + pr * 2;
                int cc = cq * 4;
                bool has2 = (pr * 2 + 1) < trows;
                const unsigned long long* pa0 =
                    (const unsigned long long*)&A[row0 * 520 + cbase + cc];
                const unsigned long long* pa1 =
                    (const unsigned long long*)&A[(row0 + 1) * 520 + cbase + cc];
                unsigned long long a00 = pa0[0], a01v = pa0[1];
                unsigned long long a10 = has2 ? pa1[0] : a00;
                unsigned long long a11 = has2 ? pa1[1] : a01v;
                const float* P0 = &P[(row0 - k0) * 17];
                const float* P1 = has2 ? (P0 + 17) : P0;
#pragma unroll
                for (int m = 0; m < 16; ++m) {
                    if (m < nb) {
                        const unsigned long long* pu =
                            (const unsigned long long*)&Us[m * 132 + cc];
                        unsigned long long u01 = pu[0], u23 = pu[1];
                        float p0 = P0[m], p1 = P1[m];
                        unsigned long long np0 = pk2(-p0, -p0);
                        unsigned long long np1 = pk2(-p1, -p1);
                        fma2(a00, u01, np0); fma2(a01v, u23, np0);
                        fma2(a10, u01, np1); fma2(a11, u23, np1);
                    }
                }
                unsigned long long* sa0 =
                    (unsigned long long*)&A[row0 * 520 + cbase + cc];
                sa0[0] = a00; sa0[1] = a01v;
                if (has2) {
                    unsigned long long* sa1 =
                        (unsigned long long*)&A[(row0 + 1) * 520 + cbase + cc];
                    sa1[0] = a10; sa1[1] = a11;
                }
            }
            __syncthreads();
        }
    }

    float* xs = P;
    const int lane = tid & 31, wid = tid >> 5;
    for (int r = 512; r >= 0; --r) {
        float part = 0.f;
        for (int c = r + 1 + tid; c <= 512; c += 512)
            part += A[r * 520 + c] * xs[c];
#pragma unroll
        for (int off = 16; off > 0; off >>= 1)
            part += __shfl_down_sync(0xffffffffu, part, off);
        if (lane == 0) red[wid] = part;
        __syncthreads();
        if (tid == 0) {
            float s = 0.f;
#pragma unroll
            for (int w2 = 0; w2 < 16; ++w2) s += red[w2];
            xs[r] = (A[r * 520 + 513] - s) / A[r * 520 + r];
        }
        __syncthreads();
    }
    for (int i2 = tid; i2 < 513; i2 += 512)
        out[b * 513 + i2] = xs[i2];
}

// ---------------------------------------------------------------------------
extern "C" void kernel_launch(void* const* d_in, const int* in_sizes, int n_in,
                              void* d_out, int out_size)
{
    const float* x   = (const float*)d_in[0];
    const float* Win = (const float*)d_in[1];
    const float* W1  = (const float*)d_in[2];
    const float* W2  = (const float*)d_in[3];
    float* out = (float*)d_out;

    for (int d = 0; d < 127; ++d) {
        int i_min = d > 63 ? d - 63 : 0;
        int i_max = d < 63 ? d : 63;
        dim3 grid(i_max - i_min + 1, 4, 2);
        scan_diag<<<grid, 256>>>(x, Win, W1, W2, d, i_min);
    }
    hth_kernel<<<dim3(45, 64), 256>>>();
    htu_kernel<<<dim3(64, 3), 256>>>(x);
    solve_kernel<<<64, 512>>>(out);
}